// round 1
// baseline (speedup 1.0000x reference)
#include <cuda_runtime.h>
#include <cuda_bf16.h>
#include <math.h>

#define Nn 2048
#define Dd 512
#define Rr 4
#define Qq 32
#define Cc 64
#define ALPHA 0.2f
#define EPSLN 1e-5f
#define NEGF  -9e15f

// ---------------- scratch (device globals; allocation-free) ----------------
__device__ float g_x[Nn * Dd];            // current node features
__device__ float g_xenc[Nn * Dd];         // encoder output (for choice layer)
__device__ float g_t[Nn * Dd];            // gate GEMM temp
__device__ float g_Wh[Rr * Nn * Dd];      // per-relation projected features
__device__ float g_go[Rr * Nn * Dd];      // att @ Wh
__device__ float g_att[Rr * Nn * Nn];     // attention (64 MB)
__device__ float g_f1[Rr * Nn];
__device__ float g_f2[Rr * Nn];
__device__ float g_qemb[Dd];
__device__ float g_qproj[Dd];

// ---------------- block reduction helpers (256 threads) ----------------
__device__ __forceinline__ float block_sum256(float v, float* sbuf) {
    __syncthreads();
    #pragma unroll
    for (int o = 16; o > 0; o >>= 1) v += __shfl_xor_sync(0xffffffffu, v, o);
    if ((threadIdx.x & 31) == 0) sbuf[threadIdx.x >> 5] = v;
    __syncthreads();
    float tot = 0.f;
    #pragma unroll
    for (int i = 0; i < 8; ++i) tot += sbuf[i];
    return tot;
}

__device__ __forceinline__ float block_max256(float v, float* sbuf) {
    __syncthreads();
    #pragma unroll
    for (int o = 16; o > 0; o >>= 1) v = fmaxf(v, __shfl_xor_sync(0xffffffffu, v, o));
    if ((threadIdx.x & 31) == 0) sbuf[threadIdx.x >> 5] = v;
    __syncthreads();
    float tot = -INFINITY;
    #pragma unroll
    for (int i = 0; i < 8; ++i) tot = fmaxf(tot, sbuf[i]);
    return tot;
}

// ---------------- SGEMM: 128x128 tile, 8x8 microtile, 256 threads ----------------
// C[M,Nc] = A[M,K] * B   (TRANSB=0: B is [K,Nc] row-major; TRANSB=1: B is [Nc,K] row-major)
template <int TRANSB>
__global__ void __launch_bounds__(256) sgemm128(
    const float* __restrict__ A, const float* __restrict__ B, float* __restrict__ C,
    int M, int Nc, int K, long sA, long sB, long sC)
{
    A += (long)blockIdx.z * sA;
    B += (long)blockIdx.z * sB;
    C += (long)blockIdx.z * sC;

    __shared__ __align__(16) float As[8][132];
    __shared__ __align__(16) float Bs[8][132];

    const int t  = threadIdx.x;
    const int tx = t & 15, ty = t >> 4;
    const int bm = blockIdx.y * 128, bn = blockIdx.x * 128;

    float acc[8][8];
    #pragma unroll
    for (int i = 0; i < 8; ++i)
        #pragma unroll
        for (int j = 0; j < 8; ++j) acc[i][j] = 0.f;

    const int lr = t >> 1;         // 0..127
    const int lk = (t & 1) * 4;    // 0 or 4

    for (int k0 = 0; k0 < K; k0 += 8) {
        float4 av = *(const float4*)(A + (long)(bm + lr) * K + k0 + lk);
        As[lk + 0][lr] = av.x; As[lk + 1][lr] = av.y;
        As[lk + 2][lr] = av.z; As[lk + 3][lr] = av.w;
        if (TRANSB) {
            float4 bv = *(const float4*)(B + (long)(bn + lr) * K + k0 + lk);
            Bs[lk + 0][lr] = bv.x; Bs[lk + 1][lr] = bv.y;
            Bs[lk + 2][lr] = bv.z; Bs[lk + 3][lr] = bv.w;
        } else {
            const int kk = t >> 5;           // 0..7
            const int nq = (t & 31) * 4;     // 0..124
            float4 bv = *(const float4*)(B + (long)(k0 + kk) * Nc + bn + nq);
            *(float4*)&Bs[kk][nq] = bv;
        }
        __syncthreads();
        #pragma unroll
        for (int k = 0; k < 8; ++k) {
            float a[8], b[8];
            *(float4*)&a[0] = *(const float4*)&As[k][ty * 4];
            *(float4*)&a[4] = *(const float4*)&As[k][64 + ty * 4];
            *(float4*)&b[0] = *(const float4*)&Bs[k][tx * 4];
            *(float4*)&b[4] = *(const float4*)&Bs[k][64 + tx * 4];
            #pragma unroll
            for (int i = 0; i < 8; ++i)
                #pragma unroll
                for (int j = 0; j < 8; ++j)
                    acc[i][j] = fmaf(a[i], b[j], acc[i][j]);
        }
        __syncthreads();
    }
    #pragma unroll
    for (int i = 0; i < 8; ++i) {
        int row = bm + ((i < 4) ? (ty * 4 + i) : (64 + ty * 4 + i - 4));
        *(float4*)(C + (long)row * Nc + bn + tx * 4) =
            make_float4(acc[i][0], acc[i][1], acc[i][2], acc[i][3]);
        *(float4*)(C + (long)row * Nc + bn + 64 + tx * 4) =
            make_float4(acc[i][4], acc[i][5], acc[i][6], acc[i][7]);
    }
}

// ---------------- question layer: qemb + qproj ----------------
__global__ void question_kernel(const float* __restrict__ qe, const float* __restrict__ wq,
                                const float* __restrict__ Wqc, const float* __restrict__ bqc,
                                float* __restrict__ qemb, float* __restrict__ qproj)
{
    __shared__ float logits[Qq];
    __shared__ float sc[Qq];
    __shared__ float marr[Dd];
    const int t = threadIdx.x;          // 512
    const int w = t >> 5, lane = t & 31;

    for (int q = w; q < Qq; q += 16) {
        float s = 0.f;
        for (int d = lane; d < Dd; d += 32) s += qe[q * Dd + d] * wq[d];
        #pragma unroll
        for (int o = 16; o > 0; o >>= 1) s += __shfl_xor_sync(0xffffffffu, s, o);
        if (lane == 0) logits[q] = s;
    }
    __syncthreads();
    if (w == 0) {
        float v = logits[lane];
        float mx = v;
        #pragma unroll
        for (int o = 16; o > 0; o >>= 1) mx = fmaxf(mx, __shfl_xor_sync(0xffffffffu, mx, o));
        float ex = __expf(v - mx);
        float sum = ex;
        #pragma unroll
        for (int o = 16; o > 0; o >>= 1) sum += __shfl_xor_sync(0xffffffffu, sum, o);
        sc[lane] = ex / sum;
    }
    __syncthreads();
    {
        float acc = 0.f, msum = 0.f;
        #pragma unroll 4
        for (int q = 0; q < Qq; ++q) { float v = qe[q * Dd + t]; acc += sc[q] * v; msum += v; }
        qemb[t] = acc;
        marr[t] = msum * (1.f / (float)Qq);
    }
    __syncthreads();
    {
        float acc = bqc[t];
        for (int d = 0; d < Dd; ++d) acc += marr[d] * Wqc[d * Dd + t];
        qproj[t] = acc;
    }
}

// ---------------- gate: p = sigmoid((xWc^T+bc)·qemb); x = p*x + (1-p)*qemb ----------------
__global__ void gate_kernel(const float* __restrict__ x_in, const float* __restrict__ tmat,
                            const float* __restrict__ bc, const float* __restrict__ qemb,
                            float* __restrict__ xout)
{
    __shared__ float sbuf[8];
    const int n = blockIdx.x, t = threadIdx.x;   // 256
    const float* trow = tmat + (long)n * Dd;
    float s = 0.f;
    for (int d = t; d < Dd; d += 256) s += (trow[d] + bc[d]) * qemb[d];
    s = block_sum256(s, sbuf);
    float p = 1.f / (1.f + __expf(-s));
    const float* xrow = x_in + (long)n * Dd;
    float* orow = xout + (long)n * Dd;
    for (int d = t; d < Dd; d += 256) orow[d] = p * xrow[d] + (1.f - p) * qemb[d];
}

// ---------------- f1/f2 = Wh · a1/a2 ----------------
__global__ void f12_kernel(const float* __restrict__ Wh, const float* __restrict__ a1,
                           const float* __restrict__ a2, float* __restrict__ f1,
                           float* __restrict__ f2)
{
    __shared__ float sbuf[8];
    const int rn = blockIdx.x;             // r*N + n
    const int r  = rn >> 11;               // N = 2048
    const float* row = Wh + (long)rn * Dd;
    const float* p1 = a1 + r * Dd;
    const float* p2 = a2 + r * Dd;
    float s1 = 0.f, s2 = 0.f;
    for (int d = threadIdx.x; d < Dd; d += 256) {
        float v = row[d];
        s1 += v * p1[d];
        s2 += v * p2[d];
    }
    s1 = block_sum256(s1, sbuf);
    s2 = block_sum256(s2, sbuf);
    if (threadIdx.x == 0) { f1[rn] = s1; f2[rn] = s2; }
}

// ---------------- masked-softmax attention row ----------------
__global__ void att_kernel(const float* __restrict__ f1, const float* __restrict__ f2,
                           const int* __restrict__ adj, float* __restrict__ att)
{
    __shared__ float sbuf[8];
    const int rn = blockIdx.x;
    const int r  = rn >> 11;
    const int* arow = adj + (long)rn * Nn;
    float* orow = att + (long)rn * Nn;
    const float f1v = f1[rn];
    const float* f2r = f2 + r * Nn;
    const int t = threadIdx.x;   // 256

    float mx = -INFINITY;
    for (int m = t; m < Nn; m += 256) {
        float e = f1v + f2r[m];
        e = e > 0.f ? e : ALPHA * e;
        e = arow[m] > 0 ? e : NEGF;
        mx = fmaxf(mx, e);
    }
    mx = block_max256(mx, sbuf);

    float sum = 0.f;
    for (int m = t; m < Nn; m += 256) {
        float e = f1v + f2r[m];
        e = e > 0.f ? e : ALPHA * e;
        e = arow[m] > 0 ? e : NEGF;
        float ex = __expf(e - mx);
        orow[m] = ex;
        sum += ex;
    }
    sum = block_sum256(sum, sbuf);
    float inv = 1.f / sum;
    for (int m = t; m < Nn; m += 256) orow[m] *= inv;
}

// ---------------- elu (+ optional LayerNorm) + max over relations ----------------
__global__ void postproc_kernel(const float* __restrict__ go, float* __restrict__ xout,
                                const float* __restrict__ g, const float* __restrict__ b,
                                int do_ln)
{
    __shared__ float sbuf[8];
    const int n = blockIdx.x, t = threadIdx.x;   // 256 threads, 2 feats each
    float m0 = -INFINITY, m1 = -INFINITY;
    for (int r = 0; r < Rr; ++r) {
        const float* row = go + (long)(r * Nn + n) * Dd;
        float v0 = row[t], v1 = row[t + 256];
        v0 = v0 > 0.f ? v0 : __expf(v0) - 1.f;
        v1 = v1 > 0.f ? v1 : __expf(v1) - 1.f;
        if (do_ln) {
            float s = block_sum256(v0 + v1, sbuf);
            float mu = s * (1.f / (float)Dd);
            float d0 = v0 - mu, d1 = v1 - mu;
            float q = block_sum256(d0 * d0 + d1 * d1, sbuf);
            float inv = rsqrtf(q * (1.f / (float)Dd) + EPSLN);
            v0 = d0 * inv * g[t] + b[t];
            v1 = d1 * inv * g[t + 256] + b[t + 256];
        }
        m0 = fmaxf(m0, v0);
        m1 = fmaxf(m1, v1);
    }
    xout[(long)n * Dd + t] = m0;
    xout[(long)n * Dd + t + 256] = m1;
}

// ---------------- copy x -> xenc ----------------
__global__ void copy_kernel(float* __restrict__ dst, const float* __restrict__ src)
{
    int i = blockIdx.x * 256 + threadIdx.x;
    dst[i] = src[i];
}

// ---------------- choice layer ----------------
__global__ void choice_kernel(const float* __restrict__ xenc, const int* __restrict__ cidx,
                              const float* __restrict__ qproj, const float* __restrict__ Wout,
                              const float* __restrict__ bout, float* __restrict__ out)
{
    __shared__ float sc[5][Cc];
    __shared__ float dw[5][Cc];
    __shared__ float lg[5];
    const int t = threadIdx.x;       // 512
    const int w = t >> 5, lane = t & 31;

    for (int p = w; p < 5 * Cc; p += 16) {
        int node = cidx[p];
        const float* row = xenc + (long)node * Dd;
        float s1 = 0.f, s2 = 0.f;
        for (int d = lane; d < Dd; d += 32) {
            float v = row[d];
            s1 += v * qproj[d];
            s2 += v * Wout[d];
        }
        #pragma unroll
        for (int o = 16; o > 0; o >>= 1) {
            s1 += __shfl_xor_sync(0xffffffffu, s1, o);
            s2 += __shfl_xor_sync(0xffffffffu, s2, o);
        }
        if (lane == 0) { sc[p / Cc][p % Cc] = s1; dw[p / Cc][p % Cc] = s2; }
    }
    __syncthreads();
    if (w < 5) {
        float v0 = sc[w][lane], v1 = sc[w][lane + 32];
        float mx = fmaxf(v0, v1);
        #pragma unroll
        for (int o = 16; o > 0; o >>= 1) mx = fmaxf(mx, __shfl_xor_sync(0xffffffffu, mx, o));
        float e0 = __expf(v0 - mx), e1 = __expf(v1 - mx);
        float s = e0 + e1;
        float l = e0 * dw[w][lane] + e1 * dw[w][lane + 32];
        #pragma unroll
        for (int o = 16; o > 0; o >>= 1) {
            s += __shfl_xor_sync(0xffffffffu, s, o);
            l += __shfl_xor_sync(0xffffffffu, l, o);
        }
        if (lane == 0) lg[w] = l / s + bout[0];
    }
    __syncthreads();
    if (t == 0) {
        float mx = lg[0];
        #pragma unroll
        for (int k = 1; k < 5; ++k) mx = fmaxf(mx, lg[k]);
        float sum = 0.f;
        #pragma unroll
        for (int k = 0; k < 5; ++k) sum += __expf(lg[k] - mx);
        float lse = mx + logf(sum);
        #pragma unroll
        for (int k = 0; k < 5; ++k) out[k] = lg[k] - lse;
    }
}

// ---------------- launcher ----------------
extern "C" void kernel_launch(void* const* d_in, const int* in_sizes, int n_in,
                              void* d_out, int out_size)
{
    const float* x    = (const float*)d_in[0];
    const int*   adj  = (const int*)  d_in[1];
    const float* qe   = (const float*)d_in[2];
    const int*   cidx = (const int*)  d_in[4];
    const float* Wc   = (const float*)d_in[5];
    const float* bc   = (const float*)d_in[6];
    const float* wq   = (const float*)d_in[7];
    const float* encW = (const float*)d_in[8];
    const float* ea1  = (const float*)d_in[9];
    const float* ea2  = (const float*)d_in[10];
    const float* decW = (const float*)d_in[11];
    const float* da1  = (const float*)d_in[12];
    const float* da2  = (const float*)d_in[13];
    const float* lng  = (const float*)d_in[14];
    const float* lnb  = (const float*)d_in[15];
    const float* Wqc  = (const float*)d_in[16];
    const float* bqc  = (const float*)d_in[17];
    const float* Wout = (const float*)d_in[18];
    const float* bout = (const float*)d_in[19];
    float* out = (float*)d_out;

    float *px, *pxenc, *pt, *pWh, *patt, *pgo, *pf1, *pf2, *pqemb, *pqproj;
    cudaGetSymbolAddress((void**)&px,     g_x);
    cudaGetSymbolAddress((void**)&pxenc,  g_xenc);
    cudaGetSymbolAddress((void**)&pt,     g_t);
    cudaGetSymbolAddress((void**)&pWh,    g_Wh);
    cudaGetSymbolAddress((void**)&patt,   g_att);
    cudaGetSymbolAddress((void**)&pgo,    g_go);
    cudaGetSymbolAddress((void**)&pf1,    g_f1);
    cudaGetSymbolAddress((void**)&pf2,    g_f2);
    cudaGetSymbolAddress((void**)&pqemb,  g_qemb);
    cudaGetSymbolAddress((void**)&pqproj, g_qproj);

    // 1) question layer
    question_kernel<<<1, 512>>>(qe, wq, Wqc, bqc, pqemb, pqproj);

    // 2) gate: t = x @ Wc^T   (NT), then elementwise gate
    sgemm128<1><<<dim3(Dd / 128, Nn / 128, 1), 256>>>(x, Wc, pt, Nn, Dd, Dd, 0, 0, 0);
    gate_kernel<<<Nn, 256>>>(x, pt, bc, pqemb, px);

    // 3) encoder: 2 heads, LN + max
    for (int h = 0; h < 2; ++h) {
        sgemm128<0><<<dim3(Dd / 128, Nn / 128, Rr), 256>>>(
            px, encW + (long)h * Rr * Dd * Dd, pWh, Nn, Dd, Dd,
            0, (long)Dd * Dd, (long)Nn * Dd);
        f12_kernel<<<Rr * Nn, 256>>>(pWh, ea1 + h * Rr * Dd, ea2 + h * Rr * Dd, pf1, pf2);
        att_kernel<<<Rr * Nn, 256>>>(pf1, pf2, adj, patt);
        sgemm128<0><<<dim3(Dd / 128, Nn / 128, Rr), 256>>>(
            patt, pWh, pgo, Nn, Dd, Nn,
            (long)Nn * Nn, (long)Nn * Dd, (long)Nn * Dd);
        postproc_kernel<<<Nn, 256>>>(pgo, px, lng, lnb, 1);
    }
    copy_kernel<<<Nn * Dd / 256, 256>>>(pxenc, px);

    // 4) decoder: 2 heads, LN only on first, write final xd straight to output
    float* xdout = (out_size >= 5 + Nn * Dd) ? (out + 5) : px;
    for (int i = 0; i < 2; ++i) {
        sgemm128<0><<<dim3(Dd / 128, Nn / 128, Rr), 256>>>(
            px, decW + (long)i * Rr * Dd * Dd, pWh, Nn, Dd, Dd,
            0, (long)Dd * Dd, (long)Nn * Dd);
        f12_kernel<<<Rr * Nn, 256>>>(pWh, da1 + i * Rr * Dd, da2 + i * Rr * Dd, pf1, pf2);
        att_kernel<<<Rr * Nn, 256>>>(pf1, pf2, adj, patt);
        sgemm128<0><<<dim3(Dd / 128, Nn / 128, Rr), 256>>>(
            patt, pWh, pgo, Nn, Dd, Nn,
            (long)Nn * Nn, (long)Nn * Dd, (long)Nn * Dd);
        postproc_kernel<<<Nn, 256>>>(pgo, (i == 1) ? xdout : px, lng, lnb, (i == 0) ? 1 : 0);
    }

    // 5) choice layer -> out[0..4]
    choice_kernel<<<1, 512>>>(pxenc, cidx, pqproj, Wout, bout, out);
}

// round 5
// speedup vs baseline: 2.1995x; 2.1995x over previous
#include <cuda_runtime.h>
#include <cuda_bf16.h>
#include <math.h>

#define Nn 2048
#define Dd 512
#define Rr 4
#define Qq 32
#define Cc 64
#define ALPHA 0.2f
#define EPSLN 1e-5f

// ---------------- scratch (device globals; allocation-free) ----------------
__device__ float g_x[Nn * Dd];
__device__ float g_xenc[Nn * Dd];
__device__ float g_t[Nn * Dd];
__device__ float g_Wh[Rr * Nn * Dd];
__device__ float g_go[Rr * Nn * Dd];
__device__ float g_att[Rr * Nn * Nn];       // unnormalized exp values
__device__ float g_f1[Rr * Nn];
__device__ float g_f2[Rr * Nn];
__device__ float g_inv[Rr * Nn];            // 1/rowsum for deferred softmax norm
__device__ unsigned g_mask[Rr * Nn * (Nn / 32)];  // adj>0 bitmask (2 MB)
__device__ float g_qemb[Dd];
__device__ float g_qproj[Dd];

// ---------------- helpers ----------------
__device__ __forceinline__ unsigned f2tf32(float x) {
    unsigned u;
    asm("cvt.rna.tf32.f32 %0, %1;" : "=r"(u) : "f"(x));
    return u;
}

__device__ __forceinline__ void mma_tf32(float c[4], const unsigned a[4], const unsigned b[2]) {
    asm volatile(
        "mma.sync.aligned.m16n8k8.row.col.f32.tf32.tf32.f32 "
        "{%0,%1,%2,%3}, {%4,%5,%6,%7}, {%8,%9}, {%0,%1,%2,%3};"
        : "+f"(c[0]), "+f"(c[1]), "+f"(c[2]), "+f"(c[3])
        : "r"(a[0]), "r"(a[1]), "r"(a[2]), "r"(a[3]), "r"(b[0]), "r"(b[1]));
}

__device__ __forceinline__ float block_sum256(float v, float* sbuf) {
    __syncthreads();
    #pragma unroll
    for (int o = 16; o > 0; o >>= 1) v += __shfl_xor_sync(0xffffffffu, v, o);
    if ((threadIdx.x & 31) == 0) sbuf[threadIdx.x >> 5] = v;
    __syncthreads();
    float tot = 0.f;
    #pragma unroll
    for (int i = 0; i < 8; ++i) tot += sbuf[i];
    return tot;
}

__device__ __forceinline__ float block_max256(float v, float* sbuf) {
    __syncthreads();
    #pragma unroll
    for (int o = 16; o > 0; o >>= 1) v = fmaxf(v, __shfl_xor_sync(0xffffffffu, v, o));
    if ((threadIdx.x & 31) == 0) sbuf[threadIdx.x >> 5] = v;
    __syncthreads();
    float tot = -INFINITY;
    #pragma unroll
    for (int i = 0; i < 8; ++i) tot = fmaxf(tot, sbuf[i]);
    return tot;
}

// ---------------- tf32 tensor-core GEMM: 128x128x16 tile, 8 warps ----------------
// C[M,N] = A[M,K] * B.  TRANSB=0: B is [K,N] row-major. TRANSB=1: B is [N,K] row-major.
// M,N multiples of 128; K multiple of 16.
template <int TRANSB>
__global__ void __launch_bounds__(256, 2) mma_gemm(
    const float* __restrict__ A, const float* __restrict__ B, float* __restrict__ C,
    int M, int N, int K, long sA, long sB, long sC)
{
    A += (long)blockIdx.z * sA;
    B += (long)blockIdx.z * sB;
    C += (long)blockIdx.z * sC;

    __shared__ unsigned As[16][132];
    __shared__ unsigned Bs[16][132];

    const int t = threadIdx.x, lane = t & 31, wid = t >> 5;
    const int bm = blockIdx.y * 128, bn = blockIdx.x * 128;
    const int wm = (wid & 3) * 32, wn = (wid >> 2) * 64;
    const int kl = lane & 3, gm = lane >> 2;

    float acc[2][8][4];
    #pragma unroll
    for (int mi = 0; mi < 2; ++mi)
        #pragma unroll
        for (int ni = 0; ni < 8; ++ni)
            #pragma unroll
            for (int c = 0; c < 4; ++c) acc[mi][ni][c] = 0.f;

    // A-tile load map: i = t + j*256 -> row = i>>2, kq = (i&3)*4 (float4 along K)
    const int rowA0 = t >> 2, kqA = (t & 3) * 4;
    // B-tile (TRANSB=0) map: k = i>>5, nq = (i&31)*4
    const int kB0 = t >> 5, nqB = (t & 31) * 4;

    float4 fa0, fa1, fb0, fb1;
    fa0 = *(const float4*)(A + (long)(bm + rowA0) * K + kqA);
    fa1 = *(const float4*)(A + (long)(bm + rowA0 + 64) * K + kqA);
    if (TRANSB) {
        fb0 = *(const float4*)(B + (long)(bn + rowA0) * K + kqA);
        fb1 = *(const float4*)(B + (long)(bn + rowA0 + 64) * K + kqA);
    } else {
        fb0 = *(const float4*)(B + (long)kB0 * N + bn + nqB);
        fb1 = *(const float4*)(B + (long)(kB0 + 8) * N + bn + nqB);
    }

    for (int k0 = 0; k0 < K; k0 += 16) {
        // stage to smem (convert to tf32)
        As[kqA + 0][rowA0] = f2tf32(fa0.x);
        As[kqA + 1][rowA0] = f2tf32(fa0.y);
        As[kqA + 2][rowA0] = f2tf32(fa0.z);
        As[kqA + 3][rowA0] = f2tf32(fa0.w);
        As[kqA + 0][rowA0 + 64] = f2tf32(fa1.x);
        As[kqA + 1][rowA0 + 64] = f2tf32(fa1.y);
        As[kqA + 2][rowA0 + 64] = f2tf32(fa1.z);
        As[kqA + 3][rowA0 + 64] = f2tf32(fa1.w);
        if (TRANSB) {
            Bs[kqA + 0][rowA0] = f2tf32(fb0.x);
            Bs[kqA + 1][rowA0] = f2tf32(fb0.y);
            Bs[kqA + 2][rowA0] = f2tf32(fb0.z);
            Bs[kqA + 3][rowA0] = f2tf32(fb0.w);
            Bs[kqA + 0][rowA0 + 64] = f2tf32(fb1.x);
            Bs[kqA + 1][rowA0 + 64] = f2tf32(fb1.y);
            Bs[kqA + 2][rowA0 + 64] = f2tf32(fb1.z);
            Bs[kqA + 3][rowA0 + 64] = f2tf32(fb1.w);
        } else {
            Bs[kB0][nqB + 0] = f2tf32(fb0.x);
            Bs[kB0][nqB + 1] = f2tf32(fb0.y);
            Bs[kB0][nqB + 2] = f2tf32(fb0.z);
            Bs[kB0][nqB + 3] = f2tf32(fb0.w);
            Bs[kB0 + 8][nqB + 0] = f2tf32(fb1.x);
            Bs[kB0 + 8][nqB + 1] = f2tf32(fb1.y);
            Bs[kB0 + 8][nqB + 2] = f2tf32(fb1.z);
            Bs[kB0 + 8][nqB + 3] = f2tf32(fb1.w);
        }
        __syncthreads();

        // prefetch next tile
        if (k0 + 16 < K) {
            int kn = k0 + 16;
            fa0 = *(const float4*)(A + (long)(bm + rowA0) * K + kn + kqA);
            fa1 = *(const float4*)(A + (long)(bm + rowA0 + 64) * K + kn + kqA);
            if (TRANSB) {
                fb0 = *(const float4*)(B + (long)(bn + rowA0) * K + kn + kqA);
                fb1 = *(const float4*)(B + (long)(bn + rowA0 + 64) * K + kn + kqA);
            } else {
                fb0 = *(const float4*)(B + (long)(kn + kB0) * N + bn + nqB);
                fb1 = *(const float4*)(B + (long)(kn + kB0 + 8) * N + bn + nqB);
            }
        }

        // compute: 2 k8 steps
        #pragma unroll
        for (int kb = 0; kb < 16; kb += 8) {
            unsigned a[2][4], b[8][2];
            #pragma unroll
            for (int mi = 0; mi < 2; ++mi) {
                int m = wm + mi * 16 + gm;
                a[mi][0] = As[kb + kl][m];
                a[mi][1] = As[kb + kl][m + 8];
                a[mi][2] = As[kb + kl + 4][m];
                a[mi][3] = As[kb + kl + 4][m + 8];
            }
            #pragma unroll
            for (int ni = 0; ni < 8; ++ni) {
                int n = wn + ni * 8 + gm;
                b[ni][0] = Bs[kb + kl][n];
                b[ni][1] = Bs[kb + kl + 4][n];
            }
            #pragma unroll
            for (int mi = 0; mi < 2; ++mi)
                #pragma unroll
                for (int ni = 0; ni < 8; ++ni)
                    mma_tf32(acc[mi][ni], a[mi], b[ni]);
        }
        __syncthreads();
    }

    // epilogue
    #pragma unroll
    for (int mi = 0; mi < 2; ++mi) {
        int row0 = bm + wm + mi * 16 + gm;
        #pragma unroll
        for (int ni = 0; ni < 8; ++ni) {
            int col = bn + wn + ni * 8 + kl * 2;
            *(float2*)(C + (long)row0 * N + col) = make_float2(acc[mi][ni][0], acc[mi][ni][1]);
            *(float2*)(C + (long)(row0 + 8) * N + col) = make_float2(acc[mi][ni][2], acc[mi][ni][3]);
        }
    }
}

// ---------------- pack adj -> bitmask ----------------
__global__ void pack_adj_kernel(const int* __restrict__ adj, unsigned* __restrict__ mask)
{
    const int row = blockIdx.x;          // Rr*Nn rows
    const int lane = threadIdx.x & 31, w = threadIdx.x >> 5;   // 256 threads
    const int* arow = adj + (long)row * Nn;
    for (int wi = w; wi < Nn / 32; wi += 8) {
        unsigned b = __ballot_sync(0xffffffffu, arow[wi * 32 + lane] > 0);
        if (lane == 0) mask[(long)row * (Nn / 32) + wi] = b;
    }
}

// ---------------- question layer: qemb + qproj ----------------
__global__ void question_kernel(const float* __restrict__ qe, const float* __restrict__ wq,
                                const float* __restrict__ Wqc, const float* __restrict__ bqc,
                                float* __restrict__ qemb, float* __restrict__ qproj)
{
    __shared__ float logits[Qq];
    __shared__ float sc[Qq];
    __shared__ float marr[Dd];
    const int t = threadIdx.x;          // 512
    const int w = t >> 5, lane = t & 31;

    for (int q = w; q < Qq; q += 16) {
        float s = 0.f;
        for (int d = lane; d < Dd; d += 32) s += qe[q * Dd + d] * wq[d];
        #pragma unroll
        for (int o = 16; o > 0; o >>= 1) s += __shfl_xor_sync(0xffffffffu, s, o);
        if (lane == 0) logits[q] = s;
    }
    __syncthreads();
    if (w == 0) {
        float v = logits[lane];
        float mx = v;
        #pragma unroll
        for (int o = 16; o > 0; o >>= 1) mx = fmaxf(mx, __shfl_xor_sync(0xffffffffu, mx, o));
        float ex = __expf(v - mx);
        float sum = ex;
        #pragma unroll
        for (int o = 16; o > 0; o >>= 1) sum += __shfl_xor_sync(0xffffffffu, sum, o);
        sc[lane] = ex / sum;
    }
    __syncthreads();
    {
        float acc = 0.f, msum = 0.f;
        #pragma unroll 4
        for (int q = 0; q < Qq; ++q) { float v = qe[q * Dd + t]; acc += sc[q] * v; msum += v; }
        qemb[t] = acc;
        marr[t] = msum * (1.f / (float)Qq);
    }
    __syncthreads();
    {
        float acc = bqc[t];
        for (int d = 0; d < Dd; ++d) acc += marr[d] * Wqc[d * Dd + t];
        qproj[t] = acc;
    }
}

// ---------------- gate ----------------
__global__ void gate_kernel(const float* __restrict__ x_in, const float* __restrict__ tmat,
                            const float* __restrict__ bc, const float* __restrict__ qemb,
                            float* __restrict__ xout)
{
    __shared__ float sbuf[8];
    const int n = blockIdx.x, t = threadIdx.x;   // 256
    const float* trow = tmat + (long)n * Dd;
    float s = 0.f;
    for (int d = t; d < Dd; d += 256) s += (trow[d] + bc[d]) * qemb[d];
    s = block_sum256(s, sbuf);
    float p = 1.f / (1.f + __expf(-s));
    const float* xrow = x_in + (long)n * Dd;
    float* orow = xout + (long)n * Dd;
    for (int d = t; d < Dd; d += 256) orow[d] = p * xrow[d] + (1.f - p) * qemb[d];
}

// ---------------- f1/f2 = Wh · a1/a2 ----------------
__global__ void f12_kernel(const float* __restrict__ Wh, const float* __restrict__ a1,
                           const float* __restrict__ a2, float* __restrict__ f1,
                           float* __restrict__ f2)
{
    __shared__ float sbuf[8];
    const int rn = blockIdx.x;
    const int r  = rn >> 11;
    const float* row = Wh + (long)rn * Dd;
    const float* p1 = a1 + r * Dd;
    const float* p2 = a2 + r * Dd;
    float s1 = 0.f, s2 = 0.f;
    for (int d = threadIdx.x; d < Dd; d += 256) {
        float v = row[d];
        s1 += v * p1[d];
        s2 += v * p2[d];
    }
    s1 = block_sum256(s1, sbuf);
    s2 = block_sum256(s2, sbuf);
    if (threadIdx.x == 0) { f1[rn] = s1; f2[rn] = s2; }
}

// ---------------- masked softmax row (unnormalized exp + invsum) ----------------
__global__ void att_kernel(const float* __restrict__ f1, const float* __restrict__ f2,
                           const unsigned* __restrict__ mask, float* __restrict__ att,
                           float* __restrict__ invs)
{
    __shared__ float sbuf[8];
    const int rn = blockIdx.x;
    const int r  = rn >> 11;
    const unsigned* mrow = mask + (long)rn * (Nn / 32);
    float* orow = att + (long)rn * Nn;
    const float f1v = f1[rn];
    const float* f2r = f2 + r * Nn;
    const int t = threadIdx.x;   // 256, 8 elems each

    float e[8];
    float mx = -INFINITY;
    #pragma unroll
    for (int i = 0; i < 8; ++i) {
        int m = t + i * 256;
        float v = f1v + f2r[m];
        v = v > 0.f ? v : ALPHA * v;
        unsigned bit = (mrow[m >> 5] >> (m & 31)) & 1u;
        e[i] = bit ? v : -1e30f;
        mx = fmaxf(mx, e[i]);
    }
    mx = block_max256(mx, sbuf);

    float sum = 0.f;
    float ex[8];
    #pragma unroll
    for (int i = 0; i < 8; ++i) {
        ex[i] = __expf(e[i] - mx);
        sum += ex[i];
    }
    sum = block_sum256(sum, sbuf);
    #pragma unroll
    for (int i = 0; i < 8; ++i) orow[t + i * 256] = ex[i];
    if (t == 0) invs[rn] = 1.f / sum;
}

// ---------------- scale + elu (+ optional LayerNorm) + max over relations ----------------
__global__ void postproc_kernel(const float* __restrict__ go, float* __restrict__ xout,
                                const float* __restrict__ g, const float* __restrict__ b,
                                const float* __restrict__ invs, int do_ln)
{
    __shared__ float sbuf[8];
    const int n = blockIdx.x, t = threadIdx.x;   // 256 threads, 2 feats each
    float m0 = -INFINITY, m1 = -INFINITY;
    for (int r = 0; r < Rr; ++r) {
        const float inv = invs[r * Nn + n];
        const float* row = go + (long)(r * Nn + n) * Dd;
        float v0 = row[t] * inv, v1 = row[t + 256] * inv;
        v0 = v0 > 0.f ? v0 : __expf(v0) - 1.f;
        v1 = v1 > 0.f ? v1 : __expf(v1) - 1.f;
        if (do_ln) {
            float s = block_sum256(v0 + v1, sbuf);
            float mu = s * (1.f / (float)Dd);
            float d0 = v0 - mu, d1 = v1 - mu;
            float q = block_sum256(d0 * d0 + d1 * d1, sbuf);
            float ivn = rsqrtf(q * (1.f / (float)Dd) + EPSLN);
            v0 = d0 * ivn * g[t] + b[t];
            v1 = d1 * ivn * g[t + 256] + b[t + 256];
        }
        m0 = fmaxf(m0, v0);
        m1 = fmaxf(m1, v1);
    }
    xout[(long)n * Dd + t] = m0;
    xout[(long)n * Dd + t + 256] = m1;
}

__global__ void copy_kernel(float* __restrict__ dst, const float* __restrict__ src)
{
    int i = blockIdx.x * 256 + threadIdx.x;
    dst[i] = src[i];
}

// ---------------- choice layer ----------------
__global__ void choice_kernel(const float* __restrict__ xenc, const int* __restrict__ cidx,
                              const float* __restrict__ qproj, const float* __restrict__ Wout,
                              const float* __restrict__ bout, float* __restrict__ out)
{
    __shared__ float sc[5][Cc];
    __shared__ float dw[5][Cc];
    __shared__ float lg[5];
    const int t = threadIdx.x;       // 512
    const int w = t >> 5, lane = t & 31;

    for (int p = w; p < 5 * Cc; p += 16) {
        int node = cidx[p];
        const float* row = xenc + (long)node * Dd;
        float s1 = 0.f, s2 = 0.f;
        for (int d = lane; d < Dd; d += 32) {
            float v = row[d];
            s1 += v * qproj[d];
            s2 += v * Wout[d];
        }
        #pragma unroll
        for (int o = 16; o > 0; o >>= 1) {
            s1 += __shfl_xor_sync(0xffffffffu, s1, o);
            s2 += __shfl_xor_sync(0xffffffffu, s2, o);
        }
        if (lane == 0) { sc[p / Cc][p % Cc] = s1; dw[p / Cc][p % Cc] = s2; }
    }
    __syncthreads();
    if (w < 5) {
        float v0 = sc[w][lane], v1 = sc[w][lane + 32];
        float mx = fmaxf(v0, v1);
        #pragma unroll
        for (int o = 16; o > 0; o >>= 1) mx = fmaxf(mx, __shfl_xor_sync(0xffffffffu, mx, o));
        float e0 = __expf(v0 - mx), e1 = __expf(v1 - mx);
        float s = e0 + e1;
        float l = e0 * dw[w][lane] + e1 * dw[w][lane + 32];
        #pragma unroll
        for (int o = 16; o > 0; o >>= 1) {
            s += __shfl_xor_sync(0xffffffffu, s, o);
            l += __shfl_xor_sync(0xffffffffu, l, o);
        }
        if (lane == 0) lg[w] = l / s + bout[0];
    }
    __syncthreads();
    if (t == 0) {
        float mx = lg[0];
        #pragma unroll
        for (int k = 1; k < 5; ++k) mx = fmaxf(mx, lg[k]);
        float sum = 0.f;
        #pragma unroll
        for (int k = 0; k < 5; ++k) sum += __expf(lg[k] - mx);
        float lse = mx + logf(sum);
        #pragma unroll
        for (int k = 0; k < 5; ++k) out[k] = lg[k] - lse;
    }
}

// ---------------- launcher ----------------
extern "C" void kernel_launch(void* const* d_in, const int* in_sizes, int n_in,
                              void* d_out, int out_size)
{
    const float* x    = (const float*)d_in[0];
    const int*   adj  = (const int*)  d_in[1];
    const float* qe   = (const float*)d_in[2];
    const int*   cidx = (const int*)  d_in[4];
    const float* Wc   = (const float*)d_in[5];
    const float* bc   = (const float*)d_in[6];
    const float* wq   = (const float*)d_in[7];
    const float* encW = (const float*)d_in[8];
    const float* ea1  = (const float*)d_in[9];
    const float* ea2  = (const float*)d_in[10];
    const float* decW = (const float*)d_in[11];
    const float* da1  = (const float*)d_in[12];
    const float* da2  = (const float*)d_in[13];
    const float* lng  = (const float*)d_in[14];
    const float* lnb  = (const float*)d_in[15];
    const float* Wqc  = (const float*)d_in[16];
    const float* bqc  = (const float*)d_in[17];
    const float* Wout = (const float*)d_in[18];
    const float* bout = (const float*)d_in[19];
    float* out = (float*)d_out;

    float *px, *pxenc, *pt, *pWh, *patt, *pgo, *pf1, *pf2, *pinv, *pqemb, *pqproj;
    unsigned* pmask;
    cudaGetSymbolAddress((void**)&px,     g_x);
    cudaGetSymbolAddress((void**)&pxenc,  g_xenc);
    cudaGetSymbolAddress((void**)&pt,     g_t);
    cudaGetSymbolAddress((void**)&pWh,    g_Wh);
    cudaGetSymbolAddress((void**)&patt,   g_att);
    cudaGetSymbolAddress((void**)&pgo,    g_go);
    cudaGetSymbolAddress((void**)&pf1,    g_f1);
    cudaGetSymbolAddress((void**)&pf2,    g_f2);
    cudaGetSymbolAddress((void**)&pinv,   g_inv);
    cudaGetSymbolAddress((void**)&pmask,  g_mask);
    cudaGetSymbolAddress((void**)&pqemb,  g_qemb);
    cudaGetSymbolAddress((void**)&pqproj, g_qproj);

    // 0) pack adjacency to bitmask (reused by all 4 layers)
    pack_adj_kernel<<<Rr * Nn, 256>>>(adj, pmask);

    // 1) question layer
    question_kernel<<<1, 512>>>(qe, wq, Wqc, bqc, pqemb, pqproj);

    // 2) gate: t = x @ Wc^T (NT), then elementwise gate
    mma_gemm<1><<<dim3(Dd / 128, Nn / 128, 1), 256>>>(x, Wc, pt, Nn, Dd, Dd, 0, 0, 0);
    gate_kernel<<<Nn, 256>>>(x, pt, bc, pqemb, px);

    // 3) encoder: 2 heads, LN + max
    for (int h = 0; h < 2; ++h) {
        mma_gemm<0><<<dim3(Dd / 128, Nn / 128, Rr), 256>>>(
            px, encW + (long)h * Rr * Dd * Dd, pWh, Nn, Dd, Dd,
            0, (long)Dd * Dd, (long)Nn * Dd);
        f12_kernel<<<Rr * Nn, 256>>>(pWh, ea1 + h * Rr * Dd, ea2 + h * Rr * Dd, pf1, pf2);
        att_kernel<<<Rr * Nn, 256>>>(pf1, pf2, pmask, patt, pinv);
        mma_gemm<0><<<dim3(Dd / 128, Nn / 128, Rr), 256>>>(
            patt, pWh, pgo, Nn, Dd, Nn,
            (long)Nn * Nn, (long)Nn * Dd, (long)Nn * Dd);
        postproc_kernel<<<Nn, 256>>>(pgo, px, lng, lnb, pinv, 1);
    }
    copy_kernel<<<Nn * Dd / 256, 256>>>(pxenc, px);

    // 4) decoder: 2 heads, LN only on first, write final xd straight to output
    float* xdout = (out_size >= 5 + Nn * Dd) ? (out + 5) : px;
    for (int i = 0; i < 2; ++i) {
        mma_gemm<0><<<dim3(Dd / 128, Nn / 128, Rr), 256>>>(
            px, decW + (long)i * Rr * Dd * Dd, pWh, Nn, Dd, Dd,
            0, (long)Dd * Dd, (long)Nn * Dd);
        f12_kernel<<<Rr * Nn, 256>>>(pWh, da1 + i * Rr * Dd, da2 + i * Rr * Dd, pf1, pf2);
        att_kernel<<<Rr * Nn, 256>>>(pf1, pf2, pmask, patt, pinv);
        mma_gemm<0><<<dim3(Dd / 128, Nn / 128, Rr), 256>>>(
            patt, pWh, pgo, Nn, Dd, Nn,
            (long)Nn * Nn, (long)Nn * Dd, (long)Nn * Dd);
        postproc_kernel<<<Nn, 256>>>(pgo, (i == 1) ? xdout : px, lng, lnb, pinv, (i == 0) ? 1 : 0);
    }

    // 5) choice layer -> out[0..4]
    choice_kernel<<<1, 512>>>(pxenc, cidx, pqproj, Wout, bout, out);
}